// round 1
// baseline (speedup 1.0000x reference)
#include <cuda_runtime.h>

#define LSEQ  2048
#define BATCH 512
#define IN    78
#define NG    16

// 64 MiB scratch for precomputed, prescaled input gates, layout [t][b][u*4+e]
__device__ float g_xg[LSEQ * BATCH * NG];

__device__ __forceinline__ float ex2f(float x) {
    float r; asm("ex2.approx.f32 %0, %1;" : "=f"(r) : "f"(x)); return r;
}
__device__ __forceinline__ float rcpf(float x) {
    float r; asm("rcp.approx.f32 %0, %1;" : "=f"(r) : "f"(x)); return r;
}

// sigmoid(x) = rcp(1 + ex2(-log2(e) * x))
// tanh(x)    = 1 - 2 * rcp(1 + ex2(+2*log2(e) * x))
#define SIG_SC  (-1.4426950408889634f)
#define TANH_SC ( 2.8853900817779268f)

// ---------------------------------------------------------------------------
// Kernel 1: xg[t][b][u*4+e] = scale_e * ( x[t][b] . W_ih0[e*4+u] + b_ih0 + b_hh0 )
// 128 rows per block, x tile staged in smem (stride 79 -> conflict-free LDS).
// ---------------------------------------------------------------------------
__global__ void __launch_bounds__(256) gemm0_kernel(
    const float* __restrict__ x,
    const float* __restrict__ Wih0,
    const float* __restrict__ bih0,
    const float* __restrict__ bhh0)
{
    __shared__ float xs[128 * 79];
    __shared__ float ws[IN * NG];
    __shared__ float bs[NG];

    const int tid = threadIdx.x;
    const int rowbase = blockIdx.x * 128;
    const float* xsrc = x + rowbase * IN;

    for (int i = tid; i < 128 * IN; i += 256) {
        int r = i / IN;
        int d = i - r * IN;
        xs[r * 79 + d] = xsrc[i];
    }
    for (int i = tid; i < IN * NG; i += 256) {
        int d = i >> 4, n = i & 15;
        int u = n >> 2, e = n & 3;
        float sc = (e == 2) ? TANH_SC : SIG_SC;
        ws[i] = Wih0[(e * 4 + u) * IN + d] * sc;
    }
    if (tid < NG) {
        int u = tid >> 2, e = tid & 3;
        float sc = (e == 2) ? TANH_SC : SIG_SC;
        bs[tid] = (bih0[e * 4 + u] + bhh0[e * 4 + u]) * sc;
    }
    __syncthreads();

    const int r  = tid & 127;
    const int n0 = (tid >> 7) * 8;

    float acc0 = bs[n0 + 0], acc1 = bs[n0 + 1], acc2 = bs[n0 + 2], acc3 = bs[n0 + 3];
    float acc4 = bs[n0 + 4], acc5 = bs[n0 + 5], acc6 = bs[n0 + 6], acc7 = bs[n0 + 7];

    const float* xrow = xs + r * 79;
    #pragma unroll 13
    for (int d = 0; d < IN; d++) {
        float xv = xrow[d];
        float4 wa = *(const float4*)(ws + d * NG + n0);
        float4 wb = *(const float4*)(ws + d * NG + n0 + 4);
        acc0 = fmaf(xv, wa.x, acc0);
        acc1 = fmaf(xv, wa.y, acc1);
        acc2 = fmaf(xv, wa.z, acc2);
        acc3 = fmaf(xv, wa.w, acc3);
        acc4 = fmaf(xv, wb.x, acc4);
        acc5 = fmaf(xv, wb.y, acc5);
        acc6 = fmaf(xv, wb.z, acc6);
        acc7 = fmaf(xv, wb.w, acc7);
    }

    float4* outp = (float4*)(g_xg + (rowbase + r) * NG + n0);
    outp[0] = make_float4(acc0, acc1, acc2, acc3);
    outp[1] = make_float4(acc4, acc5, acc6, acc7);
}

// ---------------------------------------------------------------------------
// Kernel 2: recurrent scan. 8 lanes per batch element:
//   lanes 0-3: layer0 hidden unit u (gates from xg + h0_prev . W_hh0)
//   lanes 4-7: layer1 hidden unit u, one step behind (gates from bias
//              + h0(t-1) . W_ih1 + h1(t-2) . W_hh1)
// Unified code: gate_e = base_e + sum_k a_k*w1[e][k] + sum_k q_k*w2[e][k]
//   layer0: base = xg(t), a = h0_prev, w2 = 0
//   layer1: base = bias,  a = h0_prev, q = h1_prev
// 32 blocks x 128 threads -> ~1 warp per SMSP, latency-bound chain.
// ---------------------------------------------------------------------------
__global__ void __launch_bounds__(128) scan_kernel(
    const float* __restrict__ Whh0,
    const float* __restrict__ Wih1,
    const float* __restrict__ Whh1,
    const float* __restrict__ bih1,
    const float* __restrict__ bhh1,
    const int*   __restrict__ lens,
    float*       __restrict__ out)
{
    const int tid  = threadIdx.x;
    const int lane = tid & 31;
    const int b    = blockIdx.x * 16 + (tid >> 3);
    const int u    = tid & 3;
    const bool isL1 = (tid & 4) != 0;
    const int len  = lens[b];

    float w1[4][4], w2[4][4], bias4[4];
    #pragma unroll
    for (int e = 0; e < 4; e++) {
        const float sc = (e == 2) ? TANH_SC : SIG_SC;
        const int row = e * 4 + u;
        bias4[e] = isL1 ? (bih1[row] + bhh1[row]) * sc : 0.0f;
        #pragma unroll
        for (int k = 0; k < 4; k++) {
            w1[e][k] = (isL1 ? Wih1[row * 4 + k] : Whh0[row * 4 + k]) * sc;
            w2[e][k] = isL1 ? Whh1[row * 4 + k] * sc : 0.0f;
        }
    }

    float h = 0.0f, c = 0.0f;
    const float4* xg4 = (const float4*)g_xg;     // [t][b][u] of float4
    const int bidx = b * 4 + u;                   // float4 index within a timestep
    const int gbase = lane & ~7;

    // prefetch pipeline, depth 4 (hides L2/DRAM latency off the chain)
    float4 buf[4];
    #pragma unroll
    for (int j = 0; j < 4; j++)
        buf[j] = xg4[j * (BATCH * 4) + bidx];

    for (int n0 = 0; n0 < 2052; n0 += 4) {
        float4 nbuf[4];
        #pragma unroll
        for (int j = 0; j < 4; j++) {
            int t = n0 + 4 + j;
            t = (t > LSEQ - 1) ? (LSEQ - 1) : t;
            nbuf[j] = xg4[t * (BATCH * 4) + bidx];
        }

        #pragma unroll
        for (int j = 0; j < 4; j++) {
            const int n = n0 + j;

            // exchange previous h of all 8 lanes in the group
            float a0 = __shfl_sync(0xffffffffu, h, gbase + 0);
            float a1 = __shfl_sync(0xffffffffu, h, gbase + 1);
            float a2 = __shfl_sync(0xffffffffu, h, gbase + 2);
            float a3 = __shfl_sync(0xffffffffu, h, gbase + 3);
            float q0 = __shfl_sync(0xffffffffu, h, gbase + 4);
            float q1 = __shfl_sync(0xffffffffu, h, gbase + 5);
            float q2 = __shfl_sync(0xffffffffu, h, gbase + 6);
            float q3 = __shfl_sync(0xffffffffu, h, gbase + 7);

            float xb[4];
            xb[0] = buf[j].x; xb[1] = buf[j].y; xb[2] = buf[j].z; xb[3] = buf[j].w;

            float rr[4];
            #pragma unroll
            for (int e = 0; e < 4; e++) {
                float bse = isL1 ? bias4[e] : xb[e];
                float m01 = fmaf(a1, w1[e][1], a0 * w1[e][0]);
                float m23 = fmaf(a3, w1[e][3], a2 * w1[e][2]);
                float m45 = fmaf(q1, w2[e][1], q0 * w2[e][0]);
                float m67 = fmaf(q3, w2[e][3], q2 * w2[e][2]);
                float gate = bse + ((m01 + m23) + (m45 + m67));
                rr[e] = rcpf(1.0f + ex2f(gate));
            }
            float iv = rr[0], fv = rr[1], ov = rr[3];
            float gv = fmaf(-2.0f, rr[2], 1.0f);                 // tanh(g)
            float cn = fmaf(fv, c, iv * gv);
            float tc = fmaf(-2.0f, rcpf(1.0f + ex2f(TANH_SC * cn)), 1.0f); // tanh(c)
            float hn = ov * tc;

            // layer1 must not latch the n==0 (pre-history) step
            bool upd = (!isL1) || (n >= 1);
            h = upd ? hn : 0.0f;
            c = upd ? cn : 0.0f;

            if (isL1 && n >= 1 && n <= LSEQ) {
                int t = n - 1;
                out[t * (BATCH * 4) + bidx] = (t < len) ? h : 0.0f;
            }
        }
        buf[0] = nbuf[0]; buf[1] = nbuf[1]; buf[2] = nbuf[2]; buf[3] = nbuf[3];
    }
}

extern "C" void kernel_launch(void* const* d_in, const int* in_sizes, int n_in,
                              void* d_out, int out_size)
{
    const float* x    = (const float*)d_in[0];
    const int*   lens = (const int*)  d_in[1];
    const float* Wih0 = (const float*)d_in[2];
    const float* Whh0 = (const float*)d_in[3];
    const float* bih0 = (const float*)d_in[4];
    const float* bhh0 = (const float*)d_in[5];
    const float* Wih1 = (const float*)d_in[6];
    const float* Whh1 = (const float*)d_in[7];
    const float* bih1 = (const float*)d_in[8];
    const float* bhh1 = (const float*)d_in[9];
    float* out = (float*)d_out;

    gemm0_kernel<<<(LSEQ * BATCH) / 128, 256>>>(x, Wih0, bih0, bhh0);
    scan_kernel<<<BATCH / 16, 128>>>(Whh0, Wih1, Whh1, bih1, bhh1, lens, out);
}

// round 2
// speedup vs baseline: 1.3361x; 1.3361x over previous
#include <cuda_runtime.h>

#define LSEQ  2048
#define BATCH 512
#define IN    78
#define NG    16

#define NSCAN_BLK   32
#define NGEMM_BLK   8192          // 128 rows each, 4 blocks per timestep
#define BLK_PER_SLAB 64           // 64 gemm blocks = 16 timesteps
#define NSLAB       128           // 8192 / 64
#define TSLAB       16            // timesteps per slab

// 64 MiB scratch for precomputed, prescaled input gates, layout [t][b][u*4+e]
__device__ float g_xg[LSEQ * BATCH * NG];
__device__ int   g_ready[NSLAB];

__device__ __forceinline__ float ex2f(float x) {
    float r; asm("ex2.approx.f32 %0, %1;" : "=f"(r) : "f"(x)); return r;
}
__device__ __forceinline__ float rcpf(float x) {
    float r; asm("rcp.approx.f32 %0, %1;" : "=f"(r) : "f"(x)); return r;
}
__device__ __forceinline__ int ld_acq(const int* p) {
    int v; asm volatile("ld.acquire.gpu.global.b32 %0, [%1];" : "=r"(v) : "l"(p)); return v;
}

// sigmoid(x) = rcp(1 + ex2(-log2(e) * x))
// tanh(x)    = 1 - 2 * rcp(1 + ex2(+2*log2(e) * x))
#define SIG_SC  (-1.4426950408889634f)
#define TANH_SC ( 2.8853900817779268f)

// ---------------------------------------------------------------------------
// Zero the slab-ready flags (must run before each replay of the fused kernel)
// ---------------------------------------------------------------------------
__global__ void reset_kernel() {
    if (threadIdx.x < NSLAB) g_ready[threadIdx.x] = 0;
}

// ---------------------------------------------------------------------------
// GEMM side of the fused kernel: one block = 128 (t,b) rows.
// xg[t][b][u*4+e] = scale_e * ( x[t][b] . W_ih0[e*4+u] + b_ih0 + b_hh0 )
// ---------------------------------------------------------------------------
__device__ __forceinline__ void gemm_block(
    int gbid,
    const float* __restrict__ x,
    const float* __restrict__ Wih0,
    const float* __restrict__ bih0,
    const float* __restrict__ bhh0)
{
    __shared__ float xs[128 * 79];
    __shared__ float ws[IN * NG];
    __shared__ float bs[NG];

    const int tid = threadIdx.x;
    const int rowbase = gbid * 128;
    const float* xsrc = x + rowbase * IN;

    for (int i = tid; i < 128 * IN; i += 256) {
        int r = i / IN;
        int d = i - r * IN;
        xs[r * 79 + d] = xsrc[i];
    }
    for (int i = tid; i < IN * NG; i += 256) {
        int d = i >> 4, n = i & 15;
        int u = n >> 2, e = n & 3;
        float sc = (e == 2) ? TANH_SC : SIG_SC;
        ws[i] = Wih0[(e * 4 + u) * IN + d] * sc;
    }
    if (tid < NG) {
        int u = tid >> 2, e = tid & 3;
        float sc = (e == 2) ? TANH_SC : SIG_SC;
        bs[tid] = (bih0[e * 4 + u] + bhh0[e * 4 + u]) * sc;
    }
    __syncthreads();

    const int r  = tid & 127;
    const int n0 = (tid >> 7) * 8;

    float acc0 = bs[n0 + 0], acc1 = bs[n0 + 1], acc2 = bs[n0 + 2], acc3 = bs[n0 + 3];
    float acc4 = bs[n0 + 4], acc5 = bs[n0 + 5], acc6 = bs[n0 + 6], acc7 = bs[n0 + 7];

    const float* xrow = xs + r * 79;
    #pragma unroll 13
    for (int d = 0; d < IN; d++) {
        float xv = xrow[d];
        float4 wa = *(const float4*)(ws + d * NG + n0);
        float4 wb = *(const float4*)(ws + d * NG + n0 + 4);
        acc0 = fmaf(xv, wa.x, acc0);
        acc1 = fmaf(xv, wa.y, acc1);
        acc2 = fmaf(xv, wa.z, acc2);
        acc3 = fmaf(xv, wa.w, acc3);
        acc4 = fmaf(xv, wb.x, acc4);
        acc5 = fmaf(xv, wb.y, acc5);
        acc6 = fmaf(xv, wb.z, acc6);
        acc7 = fmaf(xv, wb.w, acc7);
    }

    float4* outp = (float4*)(g_xg + (rowbase + r) * NG + n0);
    outp[0] = make_float4(acc0, acc1, acc2, acc3);
    outp[1] = make_float4(acc4, acc5, acc6, acc7);

    // release this block's contribution to its slab
    __syncthreads();
    if (tid == 0) {
        __threadfence();
        atomicAdd(&g_ready[gbid >> 6], 1);
    }
}

// ---------------------------------------------------------------------------
// Scan side of the fused kernel: 8 lanes per batch element.
//   lanes 0-3: layer0 hidden unit u   lanes 4-7: layer1 unit u (lagging 1 step)
// Carries c pre-scaled by 2*log2(e) so tanh(c) needs no extra multiply.
// ---------------------------------------------------------------------------
__device__ __forceinline__ void scan_block(
    const float* __restrict__ Whh0,
    const float* __restrict__ Wih1,
    const float* __restrict__ Whh1,
    const float* __restrict__ bih1,
    const float* __restrict__ bhh1,
    const int*   __restrict__ lens,
    float*       __restrict__ out)
{
    const int tid  = threadIdx.x;
    if (tid >= 128) return;
    const int lane = tid & 31;
    const int b    = blockIdx.x * 16 + (tid >> 3);
    const int u    = tid & 3;
    const bool isL1 = (tid & 4) != 0;
    const int len  = lens[b];

    float w1[4][4], w2[4][4], bias4[4];
    #pragma unroll
    for (int e = 0; e < 4; e++) {
        const float sc = (e == 2) ? TANH_SC : SIG_SC;
        const int row = e * 4 + u;
        bias4[e] = isL1 ? (bih1[row] + bhh1[row]) * sc : 0.0f;
        #pragma unroll
        for (int k = 0; k < 4; k++) {
            w1[e][k] = (isL1 ? Wih1[row * 4 + k] : Whh0[row * 4 + k]) * sc;
            w2[e][k] = isL1 ? Whh1[row * 4 + k] * sc : 0.0f;
        }
    }

    float h = 0.0f, cs = 0.0f;   // cs = TANH_SC * c
    const float4* xg4 = (const float4*)g_xg;
    const int bidx = b * 4 + u;
    const int gbase = lane & ~7;

    // wait for slab 0 (covers initial prefetch t=0..3)
    while (ld_acq(&g_ready[0]) < BLK_PER_SLAB) __nanosleep(64);

    float4 buf[4];
    #pragma unroll
    for (int j = 0; j < 4; j++)
        buf[j] = xg4[j * (BATCH * 4) + bidx];

    for (int n0 = 0; n0 < 2052; n0 += 4) {
        if ((n0 & 15) == 0) {
            // prefetches below reach up to t = n0 + 19 -> slab n0/16 + 1
            int s = (n0 >> 4) + 1;
            s = (s > NSLAB - 1) ? (NSLAB - 1) : s;
            while (ld_acq(&g_ready[s]) < BLK_PER_SLAB) __nanosleep(64);
        }

        float4 nbuf[4];
        #pragma unroll
        for (int j = 0; j < 4; j++) {
            int t = n0 + 4 + j;
            t = (t > LSEQ - 1) ? (LSEQ - 1) : t;
            nbuf[j] = xg4[t * (BATCH * 4) + bidx];
        }

        #pragma unroll
        for (int j = 0; j < 4; j++) {
            const int n = n0 + j;

            float a0 = __shfl_sync(0xffffffffu, h, gbase + 0);
            float a1 = __shfl_sync(0xffffffffu, h, gbase + 1);
            float a2 = __shfl_sync(0xffffffffu, h, gbase + 2);
            float a3 = __shfl_sync(0xffffffffu, h, gbase + 3);
            float q0 = __shfl_sync(0xffffffffu, h, gbase + 4);
            float q1 = __shfl_sync(0xffffffffu, h, gbase + 5);
            float q2 = __shfl_sync(0xffffffffu, h, gbase + 6);
            float q3 = __shfl_sync(0xffffffffu, h, gbase + 7);

            float xb[4];
            xb[0] = buf[j].x; xb[1] = buf[j].y; xb[2] = buf[j].z; xb[3] = buf[j].w;

            float rr[4];
            #pragma unroll
            for (int e = 0; e < 4; e++) {
                float bse = isL1 ? bias4[e] : xb[e];
                float m01 = fmaf(a1, w1[e][1], a0 * w1[e][0]);
                float m23 = fmaf(a3, w1[e][3], a2 * w1[e][2]);
                float m45 = fmaf(q1, w2[e][1], q0 * w2[e][0]);
                float m67 = fmaf(q3, w2[e][3], q2 * w2[e][2]);
                float gate = bse + ((m01 + m23) + (m45 + m67));
                rr[e] = rcpf(1.0f + ex2f(gate));
            }
            float iv = rr[0], fv = rr[1], ov = rr[3];
            // gsv = TANH_SC * tanh(g)
            float gsv = fmaf(-2.0f * TANH_SC, rr[2], TANH_SC);
            float cn  = fmaf(fv, cs, iv * gsv);                 // scaled c
            float tc  = fmaf(-2.0f, rcpf(1.0f + ex2f(cn)), 1.0f); // tanh(c)
            float hn  = ov * tc;

            bool upd = (!isL1) || (n >= 1);
            h  = upd ? hn : 0.0f;
            cs = upd ? cn : 0.0f;

            if (isL1 && n >= 1 && n <= LSEQ) {
                int t = n - 1;
                out[t * (BATCH * 4) + bidx] = (t < len) ? h : 0.0f;
            }
        }
        buf[0] = nbuf[0]; buf[1] = nbuf[1]; buf[2] = nbuf[2]; buf[3] = nbuf[3];
    }
}

// ---------------------------------------------------------------------------
// Fused kernel: blocks 0..31 = scan (resident from wave 1), rest = gemm.
// ---------------------------------------------------------------------------
__global__ void __launch_bounds__(256) fused_kernel(
    const float* __restrict__ x,
    const float* __restrict__ Wih0,
    const float* __restrict__ bih0,
    const float* __restrict__ bhh0,
    const float* __restrict__ Whh0,
    const float* __restrict__ Wih1,
    const float* __restrict__ Whh1,
    const float* __restrict__ bih1,
    const float* __restrict__ bhh1,
    const int*   __restrict__ lens,
    float*       __restrict__ out)
{
    if (blockIdx.x < NSCAN_BLK) {
        scan_block(Whh0, Wih1, Whh1, bih1, bhh1, lens, out);
    } else {
        gemm_block(blockIdx.x - NSCAN_BLK, x, Wih0, bih0, bhh0);
    }
}

extern "C" void kernel_launch(void* const* d_in, const int* in_sizes, int n_in,
                              void* d_out, int out_size)
{
    const float* x    = (const float*)d_in[0];
    const int*   lens = (const int*)  d_in[1];
    const float* Wih0 = (const float*)d_in[2];
    const float* Whh0 = (const float*)d_in[3];
    const float* bih0 = (const float*)d_in[4];
    const float* bhh0 = (const float*)d_in[5];
    const float* Wih1 = (const float*)d_in[6];
    const float* Whh1 = (const float*)d_in[7];
    const float* bih1 = (const float*)d_in[8];
    const float* bhh1 = (const float*)d_in[9];
    float* out = (float*)d_out;

    reset_kernel<<<1, 128>>>();
    fused_kernel<<<NSCAN_BLK + NGEMM_BLK, 256>>>(
        x, Wih0, bih0, bhh0, Whh0, Wih1, Whh1, bih1, bhh1, lens, out);
}